// round 16
// baseline (speedup 1.0000x reference)
#include <cuda_runtime.h>
#include <cuda_fp16.h>
#include <cstdint>

#define NNODES 50000
#define NEDGES 800000
#define DF     128
#define NBLK   196            // ceil(NNODES/256)
#define CONVBLK 6250          // NNODES*DF/4/256
#define WBLK   96             // 4*4*6 weight-transpose tiles

// ---------------------------------------------------------------------------
// Scratch (__device__ globals; no allocations allowed)
// ---------------------------------------------------------------------------
__device__ __align__(16) __half g_xh[NNODES * DF];    // activations h (fp16)
__device__ __align__(16) __half g_y[NNODES * DF];     // y = h@Wr (fp16; L3: 64-wide)
__device__ __align__(16) float  g_z[NNODES * DF];     // z = h@Wl + b (fp32)
__device__ __align__(16) __half g_w[81920];           // all W^T fp16 (6 mats)
__device__ float g_invdeg[NNODES];
__device__ int   g_deg[NNODES];
__device__ int   g_cursor[NNODES];    // scan result; fill mutates to end-ptrs
__device__ int   g_csrc[NEDGES];
__device__ int   g_counter;

// Weight buffer offsets (fp16 elements), layout [N][K=128]
#define W_L1L 0
#define W_L1R 16384
#define W_L2L 32768
#define W_L2R 49152
#define W_L3L 65536          // Wl3^T (64 rows) then Wr3^T (64 rows) contiguous
#define W_L3R 73728

__device__ __forceinline__ uint32_t smem_u32(const void* p) {
    uint32_t a;
    asm("{ .reg .u64 t; cvta.to.shared.u64 t, %1; cvt.u32.u64 %0, t; }"
        : "=r"(a) : "l"(p));
    return a;
}
__device__ __forceinline__ void ldm4(uint32_t* r, uint32_t addr) {
    asm volatile("ldmatrix.sync.aligned.m8n8.x4.shared.b16 {%0,%1,%2,%3}, [%4];"
                 : "=r"(r[0]), "=r"(r[1]), "=r"(r[2]), "=r"(r[3]) : "r"(addr));
}
__device__ __forceinline__ void mma16816(float* c, const uint32_t* a,
                                         uint32_t b0, uint32_t b1) {
    asm volatile(
        "mma.sync.aligned.m16n8k16.row.col.f32.f16.f16.f32 "
        "{%0,%1,%2,%3}, {%4,%5,%6,%7}, {%8,%9}, {%0,%1,%2,%3};"
        : "+f"(c[0]), "+f"(c[1]), "+f"(c[2]), "+f"(c[3])
        : "r"(a[0]), "r"(a[1]), "r"(a[2]), "r"(a[3]), "r"(b0), "r"(b1));
}
__device__ __forceinline__ void cpa16(uint32_t dst, const void* src) {
    asm volatile("cp.async.cg.shared.global [%0], [%1], 16;" :: "r"(dst), "l"(src));
}
#define CPA_COMMIT() asm volatile("cp.async.commit_group;" ::: "memory")
#define CPA_WAIT(n)  asm volatile("cp.async.wait_group %0;" :: "n"(n) : "memory")

// ---------------------------------------------------------------------------
// Zero deg + counter
// ---------------------------------------------------------------------------
__global__ void k_zero() {
    int i = blockIdx.x * blockDim.x + threadIdx.x;
    if (i < NNODES) g_deg[i] = 0;
    if (i == 0) g_counter = 0;
}

// ---------------------------------------------------------------------------
// Prep: [0, CONVBLK) x->fp16; then W transposes (coalesced via smem tiles).
// ---------------------------------------------------------------------------
__global__ void __launch_bounds__(256)
k_prep(const float4* __restrict__ x,
       const float* __restrict__ Wl1, const float* __restrict__ Wr1,
       const float* __restrict__ Wl2, const float* __restrict__ Wr2,
       const float* __restrict__ Wl3, const float* __restrict__ Wr3) {
    __shared__ float t[32][33];
    int b = blockIdx.x, tid = threadIdx.x;
    if (b < CONVBLK) {
        int i = b * 256 + tid;
        float4 v = x[i];
        size_t o = (size_t)i * 4;
        *(__half2*)(g_xh + o)     = __floats2half2_rn(v.x, v.y);
        *(__half2*)(g_xh + o + 2) = __floats2half2_rn(v.z, v.w);
    } else {
        int m = b - CONVBLK;                // 0..95
        int z = m >> 4, r = m & 15;
        int n0 = (r & 3) * 32, k0 = (r >> 2) * 32;
        const float* W;
        __half* dst;
        int N;
        switch (z) {
            case 0: W = Wl1; dst = g_w + W_L1L; N = 128; break;
            case 1: W = Wr1; dst = g_w + W_L1R; N = 128; break;
            case 2: W = Wl2; dst = g_w + W_L2L; N = 128; break;
            case 3: W = Wr2; dst = g_w + W_L2R; N = 128; break;
            case 4: W = Wl3; dst = g_w + W_L3L; N = 64;  break;
            default: W = Wr3; dst = g_w + W_L3R; N = 64; break;
        }
        if (n0 >= N) return;
        int tx = tid & 31, ty = tid >> 5;   // 32 x 8
#pragma unroll
        for (int rr = ty; rr < 32; rr += 8)
            t[rr][tx] = W[(size_t)(k0 + rr) * N + n0 + tx];
        __syncthreads();
#pragma unroll
        for (int rr = ty; rr < 32; rr += 8)
            dst[(size_t)(n0 + rr) * 128 + k0 + tx] = __float2half_rn(t[tx][rr]);
    }
}

// 8 edges per thread: latency-bound atomics want MLP.
__global__ void k_count_deg8(const int* __restrict__ ei) {
    int t = blockIdx.x * blockDim.x + threadIdx.x;
    if (t >= NEDGES / 8) return;
    int4 d0 = ((const int4*)(ei + NEDGES))[t * 2];
    int4 d1 = ((const int4*)(ei + NEDGES))[t * 2 + 1];
    atomicAdd(&g_deg[d0.x], 1); atomicAdd(&g_deg[d0.y], 1);
    atomicAdd(&g_deg[d0.z], 1); atomicAdd(&g_deg[d0.w], 1);
    atomicAdd(&g_deg[d1.x], 1); atomicAdd(&g_deg[d1.y], 1);
    atomicAdd(&g_deg[d1.z], 1); atomicAdd(&g_deg[d1.w], 1);
}

// Fused scan: block-local exclusive scan + atomic block offset.
__global__ void __launch_bounds__(256) k_scan_f() {
    __shared__ int warp_sums[8];
    __shared__ int boff;
    const int tid = threadIdx.x, lane = tid & 31, w = tid >> 5;
    int i = blockIdx.x * 256 + tid;
    int d = (i < NNODES) ? g_deg[i] : 0;
    int v = d;
#pragma unroll
    for (int o = 1; o < 32; o <<= 1) {
        int t = __shfl_up_sync(~0u, v, o);
        if (lane >= o) v += t;
    }
    if (lane == 31) warp_sums[w] = v;
    __syncthreads();
    if (w == 0 && lane < 8) {
        int s = warp_sums[lane];
#pragma unroll
        for (int o = 1; o < 8; o <<= 1) {
            int t = __shfl_up_sync(0xFF, s, o);
            if (lane >= o) s += t;
        }
        warp_sums[lane] = s;
    }
    __syncthreads();
    int excl = v - d + (w > 0 ? warp_sums[w - 1] : 0);
    if (tid == 255) boff = atomicAdd(&g_counter, excl + d);
    __syncthreads();
    if (i < NNODES) {
        g_cursor[i] = excl + boff;
        g_invdeg[i] = 1.0f / fmaxf((float)d, 1.0f);
    }
}

__global__ void k_fill_csr8(const int* __restrict__ ei) {
    int t = blockIdx.x * blockDim.x + threadIdx.x;
    if (t >= NEDGES / 8) return;
    int4 s0 = ((const int4*)ei)[t * 2];
    int4 s1 = ((const int4*)ei)[t * 2 + 1];
    int4 d0 = ((const int4*)(ei + NEDGES))[t * 2];
    int4 d1 = ((const int4*)(ei + NEDGES))[t * 2 + 1];
    int p0 = atomicAdd(&g_cursor[d0.x], 1);
    int p1 = atomicAdd(&g_cursor[d0.y], 1);
    int p2 = atomicAdd(&g_cursor[d0.z], 1);
    int p3 = atomicAdd(&g_cursor[d0.w], 1);
    int p4 = atomicAdd(&g_cursor[d1.x], 1);
    int p5 = atomicAdd(&g_cursor[d1.y], 1);
    int p6 = atomicAdd(&g_cursor[d1.z], 1);
    int p7 = atomicAdd(&g_cursor[d1.w], 1);
    g_csrc[p0] = s0.x; g_csrc[p1] = s0.y; g_csrc[p2] = s0.z; g_csrc[p3] = s0.w;
    g_csrc[p4] = s1.x; g_csrc[p5] = s1.y; g_csrc[p6] = s1.z; g_csrc[p7] = s1.w;
}

// ---------------------------------------------------------------------------
// Gather+relu (layers 1-2): h[i] = relu(z[i] + mean_{j in N(i)} y[j]).
// One warp/node, 4 feats/lane, 8-way neighbor prefetch.
// ---------------------------------------------------------------------------
__global__ void __launch_bounds__(256) k_gather_relu() {
    int node = (blockIdx.x * blockDim.x + threadIdx.x) >> 5;
    int lane = threadIdx.x & 31;
    if (node >= NNODES) return;
    int deg = g_deg[node];
    int start = g_cursor[node] - deg;
    const int* lst = g_csrc + start;
    const int fo = lane * 4;

    float4 a0 = make_float4(0.f, 0.f, 0.f, 0.f);
    float4 a1 = make_float4(0.f, 0.f, 0.f, 0.f);
    float4 a2 = make_float4(0.f, 0.f, 0.f, 0.f);
    float4 a3 = make_float4(0.f, 0.f, 0.f, 0.f);
    float4* accs[4] = {&a0, &a1, &a2, &a3};

    int j = 0;
    for (; j + 8 <= deg; j += 8) {
        uint2 u[8];
#pragma unroll
        for (int k = 0; k < 8; ++k)
            u[k] = *(const uint2*)(g_y + (size_t)lst[j + k] * DF + fo);
#pragma unroll
        for (int k = 0; k < 8; ++k) {
            float2 p = __half22float2(*(__half2*)&u[k].x);
            float2 q = __half22float2(*(__half2*)&u[k].y);
            float4* a = accs[k & 3];
            a->x += p.x; a->y += p.y; a->z += q.x; a->w += q.y;
        }
    }
    for (; j < deg; ++j) {
        uint2 u0 = *(const uint2*)(g_y + (size_t)lst[j] * DF + fo);
        float2 p = __half22float2(*(__half2*)&u0.x);
        float2 q = __half22float2(*(__half2*)&u0.y);
        a0.x += p.x; a0.y += p.y; a0.z += q.x; a0.w += q.y;
    }
    float s = g_invdeg[node];
    float4 z = *(const float4*)(g_z + (size_t)node * DF + fo);
    float hx = fmaxf(z.x + (a0.x + a1.x + a2.x + a3.x) * s, 0.f);
    float hy = fmaxf(z.y + (a0.y + a1.y + a2.y + a3.y) * s, 0.f);
    float hz = fmaxf(z.z + (a0.z + a1.z + a2.z + a3.z) * s, 0.f);
    float hw = fmaxf(z.w + (a0.w + a1.w + a2.w + a3.w) * s, 0.f);
    size_t o = (size_t)node * DF + fo;
    *(__half2*)(g_xh + o)     = __floats2half2_rn(hx, hy);
    *(__half2*)(g_xh + o + 2) = __floats2half2_rn(hz, hw);
}

// ---------------------------------------------------------------------------
// Gather64 (layer 3): out[i] += mean_{j in N(i)} y3[j]  (y3 in g_y, 64-wide)
// ---------------------------------------------------------------------------
__global__ void __launch_bounds__(256) k_gather64(float* __restrict__ outF) {
    int node = (blockIdx.x * blockDim.x + threadIdx.x) >> 5;
    int lane = threadIdx.x & 31;
    if (node >= NNODES) return;
    int deg = g_deg[node];
    int start = g_cursor[node] - deg;
    const int* lst = g_csrc + start;
    const int fo = lane * 2;

    float2 a0 = make_float2(0.f, 0.f), a1 = make_float2(0.f, 0.f);
    float2 a2 = make_float2(0.f, 0.f), a3 = make_float2(0.f, 0.f);
    float2* accs[4] = {&a0, &a1, &a2, &a3};

    int j = 0;
    for (; j + 8 <= deg; j += 8) {
        __half2 u[8];
#pragma unroll
        for (int k = 0; k < 8; ++k)
            u[k] = *(const __half2*)(g_y + (size_t)lst[j + k] * 64 + fo);
#pragma unroll
        for (int k = 0; k < 8; ++k) {
            float2 p = __half22float2(u[k]);
            float2* a = accs[k & 3];
            a->x += p.x; a->y += p.y;
        }
    }
    for (; j < deg; ++j) {
        float2 p = __half22float2(*(const __half2*)(g_y + (size_t)lst[j] * 64 + fo));
        a0.x += p.x; a0.y += p.y;
    }
    float s = g_invdeg[node];
    float2* po = (float2*)(outF + (size_t)node * 64 + fo);
    float2 cur = *po;
    cur.x += (a0.x + a1.x + a2.x + a3.x) * s;
    cur.y += (a0.y + a1.y + a2.y + a3.y) * s;
    *po = cur;
}

// ---------------------------------------------------------------------------
// Pipelined fp16 GEMM, 2-segment A (K=128), B = one 128-row matrix.
// MODE 0 (L1/L2): grid.y selects: y==0 -> z = h@Wl + bias (fp32, g_z)
//                                 y==1 -> y = h@Wr (fp16, g_y)
// MODE 1 (L3):    B = [Wl3|Wr3]; col<64 -> outF = h@Wl3 + bias (fp32)
//                                col>=64 -> y3 (fp16, g_y 64-wide)
// ---------------------------------------------------------------------------
#define ROWA 72
#define ROWB 136

template<int MODE>
__global__ void __launch_bounds__(256, 2)
k_gemm_mma(const __half* __restrict__ bl, const __half* __restrict__ br,
           const float* __restrict__ bias, float* __restrict__ outF) {
    extern __shared__ __align__(16) __half smem[];
    const int tid = threadIdx.x;
    const int lane = tid & 31, wid = tid >> 5;
    const int warp_m = wid >> 2, warp_n = wid & 3;
    const int m0 = blockIdx.x * 128;
    const bool yHalf = (MODE == 0) && (blockIdx.y == 1);

    const uint32_t aBase = smem_u32(smem);
    const uint32_t bBase = aBase + 2u * 128 * ROWA * 2;

    const int aLaneOff = (warp_m * 64 + (lane & 15)) * ROWA + (lane >> 4) * 8;
    const int bLaneOff = (warp_n * 32 + (lane & 7) + ((lane >> 4) & 1) * 8) * ROWB
                       + ((lane >> 3) & 1) * 8;

    const __half* bMat = yHalf ? br : bl;

    // ---- Prologue: B (128 rows x 128 halves) + both A segments ----
    {
#pragma unroll
        for (int i = 0; i < 8; ++i) {
            int idx = tid + i * 256;
            int row = idx >> 4, q = idx & 15;
            cpa16(bBase + (uint32_t)(row * ROWB + q * 8) * 2,
                  bMat + (size_t)row * DF + q * 8);
        }
        // A seg 0 (k<64) and seg 1 (k>=64)
#pragma unroll
        for (int s = 0; s < 2; ++s) {
            const __half* ap = g_xh + s * 64;
            uint32_t dst0 = aBase + (uint32_t)s * 128 * ROWA * 2;
#pragma unroll
            for (int i = 0; i < 4; ++i) {
                int idx = tid + i * 256;
                int row = idx >> 3, q = idx & 7;
                int grow = m0 + row;
                if (grow > NNODES - 1) grow = NNODES - 1;   // clamp: unused rows
                cpa16(dst0 + (uint32_t)(row * ROWA + q * 8) * 2,
                      ap + (size_t)grow * DF + q * 8);
            }
        }
        CPA_COMMIT();
    }

    float acc[4][4][4];
#pragma unroll
    for (int mt = 0; mt < 4; ++mt)
#pragma unroll
        for (int nt = 0; nt < 4; ++nt)
#pragma unroll
            for (int r = 0; r < 4; ++r) acc[mt][nt][r] = 0.f;

    CPA_WAIT(0);
    __syncthreads();

#pragma unroll
    for (int s = 0; s < 2; ++s) {
        const uint32_t aB = aBase + (uint32_t)s * 128 * ROWA * 2;
        const int bOff = s * 64;
#pragma unroll
        for (int kk = 0; kk < 4; ++kk) {
            uint32_t a[4][4];
#pragma unroll
            for (int mt = 0; mt < 4; ++mt)
                ldm4(a[mt], aB + 2u * (aLaneOff + mt * 16 * ROWA + kk * 16));
            uint32_t b[2][4];
#pragma unroll
            for (int np = 0; np < 2; ++np)
                ldm4(b[np], bBase + 2u * (bOff + bLaneOff + np * 16 * ROWB + kk * 16));
#pragma unroll
            for (int mt = 0; mt < 4; ++mt)
#pragma unroll
                for (int np = 0; np < 2; ++np) {
                    mma16816(acc[mt][np * 2 + 0], a[mt], b[np][0], b[np][1]);
                    mma16816(acc[mt][np * 2 + 1], a[mt], b[np][2], b[np][3]);
                }
        }
    }

    // ---- Epilogue ----
#pragma unroll
    for (int mt = 0; mt < 4; ++mt) {
        int row0 = m0 + warp_m * 64 + mt * 16 + (lane >> 2);
#pragma unroll
        for (int nt = 0; nt < 4; ++nt) {
            int col = warp_n * 32 + nt * 8 + (lane & 3) * 2;
#pragma unroll
            for (int half = 0; half < 2; ++half) {
                int row = row0 + half * 8;
                if (row >= NNODES) continue;
                float v0 = acc[mt][nt][half * 2 + 0];
                float v1 = acc[mt][nt][half * 2 + 1];
                if (MODE == 0) {
                    if (yHalf) {
                        *(__half2*)(g_y + (size_t)row * 128 + col) =
                            __floats2half2_rn(v0, v1);
                    } else {
                        v0 += bias[col];
                        v1 += bias[col + 1];
                        *(float2*)(g_z + (size_t)row * 128 + col) =
                            make_float2(v0, v1);
                    }
                } else {
                    if (col < 64) {
                        v0 += bias[col];
                        v1 += bias[col + 1];
                        *(float2*)(outF + (size_t)row * 64 + col) =
                            make_float2(v0, v1);
                    } else {
                        *(__half2*)(g_y + (size_t)row * 64 + (col - 64)) =
                            __floats2half2_rn(v0, v1);
                    }
                }
            }
        }
    }
}

// ---------------------------------------------------------------------------
// Launch — CSR build on main stream overlaps prep + GEMM1 on s2.
// ---------------------------------------------------------------------------
extern "C" void kernel_launch(void* const* d_in, const int* in_sizes, int n_in,
                              void* d_out, int out_size) {
    const float* x   = (const float*)d_in[0];
    const int*   ei  = (const int*)d_in[1];
    const float* Wl1 = (const float*)d_in[2];
    const float* Wr1 = (const float*)d_in[3];
    const float* b1  = (const float*)d_in[4];
    const float* Wl2 = (const float*)d_in[5];
    const float* Wr2 = (const float*)d_in[6];
    const float* b2  = (const float*)d_in[7];
    const float* Wl3 = (const float*)d_in[8];
    const float* Wr3 = (const float*)d_in[9];
    const float* b3  = (const float*)d_in[10];
    float* out = (float*)d_out;

    __half* w = nullptr;
    cudaGetSymbolAddress((void**)&w, g_w);

    const int ZB = 256;
    const int edge8Blocks = (NEDGES / 8 + ZB - 1) / ZB;     // 391
    const int gathBlocks  = (NNODES * 32 + ZB - 1) / ZB;    // 6250
    const int gemmBlocks  = (NNODES + 127) / 128;           // 391
    const int SMEM = (2 * 128 * ROWA + 128 * ROWB) * 2;     // 71680

    cudaFuncSetAttribute(k_gemm_mma<0>,
                         cudaFuncAttributeMaxDynamicSharedMemorySize, SMEM);
    cudaFuncSetAttribute(k_gemm_mma<1>,
                         cudaFuncAttributeMaxDynamicSharedMemorySize, SMEM);

    cudaStream_t s2;
    cudaEvent_t eFork, eJoin;
    cudaStreamCreateWithFlags(&s2, cudaStreamNonBlocking);
    cudaEventCreateWithFlags(&eFork, cudaEventDisableTiming);
    cudaEventCreateWithFlags(&eJoin, cudaEventDisableTiming);

    // Main: zero; fork prep + GEMM1 (independent of CSR) to s2; CSR here.
    k_zero<<<NBLK, ZB>>>();
    cudaEventRecord(eFork, 0);
    cudaStreamWaitEvent(s2, eFork, 0);
    k_prep<<<CONVBLK + WBLK, ZB, 0, s2>>>((const float4*)x,
                                          Wl1, Wr1, Wl2, Wr2, Wl3, Wr3);
    k_gemm_mma<0><<<dim3(gemmBlocks, 2), 256, SMEM, s2>>>(
        w + W_L1L, w + W_L1R, b1, nullptr);
    cudaEventRecord(eJoin, s2);

    k_count_deg8<<<edge8Blocks, ZB>>>(ei);
    k_scan_f<<<NBLK, ZB>>>();
    k_fill_csr8<<<edge8Blocks, ZB>>>(ei);

    cudaStreamWaitEvent(0, eJoin, 0);   // join: gather needs z,y and CSR

    // ---- Layer 1 finish: h1 = relu(z + mean(y)) ----
    k_gather_relu<<<gathBlocks, ZB>>>();

    // ---- Layer 2 ----
    k_gemm_mma<0><<<dim3(gemmBlocks, 2), 256, SMEM>>>(
        w + W_L2L, w + W_L2R, b2, nullptr);
    k_gather_relu<<<gathBlocks, ZB>>>();

    // ---- Layer 3: GEMM (out partial + y3), then 64-wide gather-add ----
    k_gemm_mma<1><<<gemmBlocks, 256, SMEM>>>(w + W_L3L, nullptr, b3, out);
    k_gather64<<<gathBlocks, ZB>>>(out);
}

// round 17
// speedup vs baseline: 1.1308x; 1.1308x over previous
#include <cuda_runtime.h>
#include <cuda_fp16.h>
#include <cstdint>

#define NNODES 50000
#define NEDGES 800000
#define DF     128
#define NBLK   196            // ceil(NNODES/256)
#define CONVBLK 6250          // NNODES*DF/4/256
#define WBLK   96             // 4*4*6 weight-transpose tiles

// ---------------------------------------------------------------------------
// Scratch (__device__ globals; no allocations allowed)
// ---------------------------------------------------------------------------
__device__ __align__(16) __half g_xh[NNODES * DF];    // activations (fp16)
__device__ __align__(16) __half g_agh[NNODES * DF];   // agg (L1-2) / y3 (L3, 64-wide)
__device__ __align__(16) __half g_w[81920];           // all W^T fp16 (6 mats)
__device__ float g_invdeg[NNODES];
__device__ int   g_deg[NNODES];
__device__ int   g_cursor[NNODES];    // scan result; fill mutates to end-ptrs
__device__ int   g_csrc[NEDGES];
__device__ int   g_counter;

// Weight buffer offsets (fp16 elements), layout [N][K=128]
#define W_L1L 0
#define W_L1R 16384
#define W_L2L 32768
#define W_L2R 49152
#define W_L3L 65536          // Wl3^T (64 rows) then Wr3^T (64 rows) contiguous
#define W_L3R 73728

__device__ __forceinline__ uint32_t smem_u32(const void* p) {
    uint32_t a;
    asm("{ .reg .u64 t; cvta.to.shared.u64 t, %1; cvt.u32.u64 %0, t; }"
        : "=r"(a) : "l"(p));
    return a;
}
__device__ __forceinline__ void ldm4(uint32_t* r, uint32_t addr) {
    asm volatile("ldmatrix.sync.aligned.m8n8.x4.shared.b16 {%0,%1,%2,%3}, [%4];"
                 : "=r"(r[0]), "=r"(r[1]), "=r"(r[2]), "=r"(r[3]) : "r"(addr));
}
__device__ __forceinline__ void mma16816(float* c, const uint32_t* a,
                                         uint32_t b0, uint32_t b1) {
    asm volatile(
        "mma.sync.aligned.m16n8k16.row.col.f32.f16.f16.f32 "
        "{%0,%1,%2,%3}, {%4,%5,%6,%7}, {%8,%9}, {%0,%1,%2,%3};"
        : "+f"(c[0]), "+f"(c[1]), "+f"(c[2]), "+f"(c[3])
        : "r"(a[0]), "r"(a[1]), "r"(a[2]), "r"(a[3]), "r"(b0), "r"(b1));
}
__device__ __forceinline__ void cpa16(uint32_t dst, const void* src) {
    asm volatile("cp.async.cg.shared.global [%0], [%1], 16;" :: "r"(dst), "l"(src));
}
#define CPA_COMMIT() asm volatile("cp.async.commit_group;" ::: "memory")
#define CPA_WAIT(n)  asm volatile("cp.async.wait_group %0;" :: "n"(n) : "memory")

// ---------------------------------------------------------------------------
// Zero deg + counter (must precede count)
// ---------------------------------------------------------------------------
__global__ void k_zero() {
    int i = blockIdx.x * blockDim.x + threadIdx.x;
    if (i < NNODES) g_deg[i] = 0;
    if (i == 0) g_counter = 0;
}

// ---------------------------------------------------------------------------
// Prep (independent of CSR chain): [0, CONVBLK) x->fp16; then W transposes.
// ---------------------------------------------------------------------------
__global__ void __launch_bounds__(256)
k_prep(const float4* __restrict__ x,
       const float* __restrict__ Wl1, const float* __restrict__ Wr1,
       const float* __restrict__ Wl2, const float* __restrict__ Wr2,
       const float* __restrict__ Wl3, const float* __restrict__ Wr3) {
    __shared__ float t[32][33];
    int b = blockIdx.x, tid = threadIdx.x;
    if (b < CONVBLK) {
        int i = b * 256 + tid;
        float4 v = x[i];
        size_t o = (size_t)i * 4;
        *(__half2*)(g_xh + o)     = __floats2half2_rn(v.x, v.y);
        *(__half2*)(g_xh + o + 2) = __floats2half2_rn(v.z, v.w);
    } else {
        int m = b - CONVBLK;                // 0..95
        int z = m >> 4, r = m & 15;
        int n0 = (r & 3) * 32, k0 = (r >> 2) * 32;
        const float* W;
        __half* dst;
        int N;
        switch (z) {
            case 0: W = Wl1; dst = g_w + W_L1L; N = 128; break;
            case 1: W = Wr1; dst = g_w + W_L1R; N = 128; break;
            case 2: W = Wl2; dst = g_w + W_L2L; N = 128; break;
            case 3: W = Wr2; dst = g_w + W_L2R; N = 128; break;
            case 4: W = Wl3; dst = g_w + W_L3L; N = 64;  break;
            default: W = Wr3; dst = g_w + W_L3R; N = 64; break;
        }
        if (n0 >= N) return;
        int tx = tid & 31, ty = tid >> 5;   // 32 x 8
#pragma unroll
        for (int rr = ty; rr < 32; rr += 8)
            t[rr][tx] = W[(size_t)(k0 + rr) * N + n0 + tx];
        __syncthreads();
#pragma unroll
        for (int rr = ty; rr < 32; rr += 8)
            dst[(size_t)(n0 + rr) * 128 + k0 + tx] = __float2half_rn(t[tx][rr]);
    }
}

// 2 edges per thread, 1563 blocks: DRAM-latency-bound wants max warps.
__global__ void k_count_deg2(const int* __restrict__ ei) {
    int t = blockIdx.x * blockDim.x + threadIdx.x;
    if (t >= NEDGES / 2) return;
    int2 d = ((const int2*)(ei + NEDGES))[t];
    atomicAdd(&g_deg[d.x], 1);
    atomicAdd(&g_deg[d.y], 1);
}

// Fused scan: block-local exclusive scan + atomic block offset (disjoint
// ranges in arbitrary order — slot order is already nondeterministic).
__global__ void __launch_bounds__(256) k_scan_f() {
    __shared__ int warp_sums[8];
    __shared__ int boff;
    const int tid = threadIdx.x, lane = tid & 31, w = tid >> 5;
    int i = blockIdx.x * 256 + tid;
    int d = (i < NNODES) ? g_deg[i] : 0;
    int v = d;
#pragma unroll
    for (int o = 1; o < 32; o <<= 1) {
        int t = __shfl_up_sync(~0u, v, o);
        if (lane >= o) v += t;
    }
    if (lane == 31) warp_sums[w] = v;
    __syncthreads();
    if (w == 0 && lane < 8) {
        int s = warp_sums[lane];
#pragma unroll
        for (int o = 1; o < 8; o <<= 1) {
            int t = __shfl_up_sync(0xFF, s, o);
            if (lane >= o) s += t;
        }
        warp_sums[lane] = s;
    }
    __syncthreads();
    int excl = v - d + (w > 0 ? warp_sums[w - 1] : 0);
    if (tid == 255) boff = atomicAdd(&g_counter, excl + d);
    __syncthreads();
    if (i < NNODES) {
        g_cursor[i] = excl + boff;
        g_invdeg[i] = 1.0f / fmaxf((float)d, 1.0f);
    }
}

// 2 edges per thread, 1563 blocks.
__global__ void k_fill_csr2(const int* __restrict__ ei) {
    int t = blockIdx.x * blockDim.x + threadIdx.x;
    if (t >= NEDGES / 2) return;
    int2 s = ((const int2*)ei)[t];
    int2 d = ((const int2*)(ei + NEDGES))[t];
    int p0 = atomicAdd(&g_cursor[d.x], 1);
    int p1 = atomicAdd(&g_cursor[d.y], 1);
    g_csrc[p0] = s.x;
    g_csrc[p1] = s.y;
}

// After fill, cursor[i] = row end; start = end - deg.
// ---------------------------------------------------------------------------
// Gather (layers 1-2): 128-feature neighbor mean; one warp/node, 4 feats/lane.
// 8-way prefetch: 8 independent L2 loads in flight per warp.
// ---------------------------------------------------------------------------
__global__ void __launch_bounds__(256) k_gather() {
    int node = (blockIdx.x * blockDim.x + threadIdx.x) >> 5;
    int lane = threadIdx.x & 31;
    if (node >= NNODES) return;
    int deg = g_deg[node];
    int start = g_cursor[node] - deg;
    const int* lst = g_csrc + start;
    const int fo = lane * 4;

    float4 a0 = make_float4(0.f, 0.f, 0.f, 0.f);
    float4 a1 = make_float4(0.f, 0.f, 0.f, 0.f);
    float4 a2 = make_float4(0.f, 0.f, 0.f, 0.f);
    float4 a3 = make_float4(0.f, 0.f, 0.f, 0.f);
    float4* accs[4] = {&a0, &a1, &a2, &a3};

    int j = 0;
    for (; j + 8 <= deg; j += 8) {
        uint2 u[8];
#pragma unroll
        for (int k = 0; k < 8; ++k)
            u[k] = *(const uint2*)(g_xh + (size_t)lst[j + k] * DF + fo);
#pragma unroll
        for (int k = 0; k < 8; ++k) {
            float2 p = __half22float2(*(__half2*)&u[k].x);
            float2 q = __half22float2(*(__half2*)&u[k].y);
            float4* a = accs[k & 3];
            a->x += p.x; a->y += p.y; a->z += q.x; a->w += q.y;
        }
    }
    for (; j < deg; ++j) {
        uint2 u0 = *(const uint2*)(g_xh + (size_t)lst[j] * DF + fo);
        float2 p = __half22float2(*(__half2*)&u0.x);
        float2 q = __half22float2(*(__half2*)&u0.y);
        a0.x += p.x; a0.y += p.y; a0.z += q.x; a0.w += q.y;
    }
    float s = g_invdeg[node];
    size_t o = (size_t)node * DF + fo;
    *(__half2*)(g_agh + o)     = __floats2half2_rn((a0.x + a1.x + a2.x + a3.x) * s,
                                                   (a0.y + a1.y + a2.y + a3.y) * s);
    *(__half2*)(g_agh + o + 2) = __floats2half2_rn((a0.z + a1.z + a2.z + a3.z) * s,
                                                   (a0.w + a1.w + a2.w + a3.w) * s);
}

// ---------------------------------------------------------------------------
// Gather64 (layer 3): out[i] += mean_{j in N(i)} y3[j]  (y3 in g_agh, 64-wide)
// ---------------------------------------------------------------------------
__global__ void __launch_bounds__(256) k_gather64(float* __restrict__ outF) {
    int node = (blockIdx.x * blockDim.x + threadIdx.x) >> 5;
    int lane = threadIdx.x & 31;
    if (node >= NNODES) return;
    int deg = g_deg[node];
    int start = g_cursor[node] - deg;
    const int* lst = g_csrc + start;
    const int fo = lane * 2;

    float2 a0 = make_float2(0.f, 0.f), a1 = make_float2(0.f, 0.f);
    float2 a2 = make_float2(0.f, 0.f), a3 = make_float2(0.f, 0.f);
    float2* accs[4] = {&a0, &a1, &a2, &a3};

    int j = 0;
    for (; j + 8 <= deg; j += 8) {
        __half2 u[8];
#pragma unroll
        for (int k = 0; k < 8; ++k)
            u[k] = *(const __half2*)(g_agh + (size_t)lst[j + k] * 64 + fo);
#pragma unroll
        for (int k = 0; k < 8; ++k) {
            float2 p = __half22float2(u[k]);
            float2* a = accs[k & 3];
            a->x += p.x; a->y += p.y;
        }
    }
    for (; j < deg; ++j) {
        float2 p = __half22float2(*(const __half2*)(g_agh + (size_t)lst[j] * 64 + fo));
        a0.x += p.x; a0.y += p.y;
    }
    float s = g_invdeg[node];
    float2* po = (float2*)(outF + (size_t)node * 64 + fo);
    float2 cur = *po;
    cur.x += (a0.x + a1.x + a2.x + a3.x) * s;
    cur.y += (a0.y + a1.y + a2.y + a3.y) * s;
    *po = cur;
}

// ---------------------------------------------------------------------------
// Pipelined fp16 GEMM, TN=128, 2 CTAs/SM.
// MODE 0 (layers 1-2): D = A@Wr + X@Wl (4 segs); +bias, relu, fp16 -> g_xh
// MODE 1 (layer 3):    D = X@[Wl3|Wr3]  (2 segs);
//     cols<64: +bias -> fp32 outF (partial); cols>=64: y3 fp16 -> g_agh
// ---------------------------------------------------------------------------
#define ROWA 72
#define ROWB 136

template<int MODE>
__global__ void __launch_bounds__(256, 2)
k_gemm_mma(const __half* __restrict__ bl, const __half* __restrict__ br,
           const float* __restrict__ bias, float* __restrict__ outF) {
    extern __shared__ __align__(16) __half smem[];
    constexpr int NSEG = (MODE == 0) ? 4 : 2;
    constexpr int BROWS = (MODE == 0) ? 256 : 128;

    const int tid = threadIdx.x;
    const int lane = tid & 31, wid = tid >> 5;
    const int warp_m = wid >> 2, warp_n = wid & 3;
    const int m0 = blockIdx.x * 128;

    const uint32_t aBase = smem_u32(smem);
    const uint32_t bBase = aBase + 2u * 128 * ROWA * 2;

    const int aLaneOff = (warp_m * 64 + (lane & 15)) * ROWA + (lane >> 4) * 8;
    const int bLaneOff = (warp_n * 32 + (lane & 7) + ((lane >> 4) & 1) * 8) * ROWB
                       + ((lane >> 3) & 1) * 8;

    const __half* aSrc[4];
    int bOffs[4];
    if (MODE == 0) {
        aSrc[0] = g_agh; aSrc[1] = g_agh + 64; aSrc[2] = g_xh; aSrc[3] = g_xh + 64;
        bOffs[0] = 128 * ROWB; bOffs[1] = 128 * ROWB + 64; bOffs[2] = 0; bOffs[3] = 64;
    } else {
        aSrc[0] = g_xh; aSrc[1] = g_xh + 64;
        bOffs[0] = 0; bOffs[1] = 64;
    }

    auto issueA = [&](int s) {
        const __half* ap = aSrc[s];
        uint32_t dst0 = aBase + (uint32_t)(s & 1) * 128 * ROWA * 2;
#pragma unroll
        for (int i = 0; i < 4; ++i) {
            int idx = tid + i * 256;
            int row = idx >> 3, q = idx & 7;
            int grow = m0 + row;
            if (grow > NNODES - 1) grow = NNODES - 1;   // clamp: rows unused
            cpa16(dst0 + (uint32_t)(row * ROWA + q * 8) * 2,
                  ap + (size_t)grow * DF + q * 8);
        }
    };

    {
#pragma unroll
        for (int i = 0; i < (BROWS * 16) / 256; ++i) {
            int idx = tid + i * 256;
            int row = idx >> 4, q = idx & 15;
            const __half* src = (MODE == 0 && row >= 128)
                                ? br + (size_t)(row - 128) * DF + q * 8
                                : bl + (size_t)row * DF + q * 8;
            cpa16(bBase + (uint32_t)(row * ROWB + q * 8) * 2, src);
        }
        issueA(0);
        CPA_COMMIT();
        if (NSEG > 1) { issueA(1); CPA_COMMIT(); }
    }

    float acc[4][4][4];
#pragma unroll
    for (int mt = 0; mt < 4; ++mt)
#pragma unroll
        for (int nt = 0; nt < 4; ++nt)
#pragma unroll
            for (int r = 0; r < 4; ++r) acc[mt][nt][r] = 0.f;

#pragma unroll
    for (int s = 0; s < NSEG; ++s) {
        if (s < NSEG - 1) { CPA_WAIT(1); } else { CPA_WAIT(0); }
        __syncthreads();

        const uint32_t aB = aBase + (uint32_t)(s & 1) * 128 * ROWA * 2;
        const int bOff = bOffs[s];
#pragma unroll
        for (int kk = 0; kk < 4; ++kk) {
            uint32_t a[4][4];
#pragma unroll
            for (int mt = 0; mt < 4; ++mt)
                ldm4(a[mt], aB + 2u * (aLaneOff + mt * 16 * ROWA + kk * 16));
            uint32_t b[2][4];
#pragma unroll
            for (int np = 0; np < 2; ++np)
                ldm4(b[np], bBase + 2u * (bOff + bLaneOff + np * 16 * ROWB + kk * 16));
#pragma unroll
            for (int mt = 0; mt < 4; ++mt)
#pragma unroll
                for (int np = 0; np < 2; ++np) {
                    mma16816(acc[mt][np * 2 + 0], a[mt], b[np][0], b[np][1]);
                    mma16816(acc[mt][np * 2 + 1], a[mt], b[np][2], b[np][3]);
                }
        }
        __syncthreads();
        if (s + 2 < NSEG) { issueA(s + 2); CPA_COMMIT(); }
    }

    // ---- Epilogue ----
#pragma unroll
    for (int mt = 0; mt < 4; ++mt) {
        int row0 = m0 + warp_m * 64 + mt * 16 + (lane >> 2);
#pragma unroll
        for (int nt = 0; nt < 4; ++nt) {
            int col = warp_n * 32 + nt * 8 + (lane & 3) * 2;
#pragma unroll
            for (int half = 0; half < 2; ++half) {
                int row = row0 + half * 8;
                if (row >= NNODES) continue;
                float v0 = acc[mt][nt][half * 2 + 0];
                float v1 = acc[mt][nt][half * 2 + 1];
                if (MODE == 0) {
                    v0 = fmaxf(v0 + bias[col], 0.f);
                    v1 = fmaxf(v1 + bias[col + 1], 0.f);
                    *(__half2*)(g_xh + (size_t)row * 128 + col) =
                        __floats2half2_rn(v0, v1);
                } else {
                    if (col < 64) {
                        v0 += bias[col];
                        v1 += bias[col + 1];
                        *(float2*)(outF + (size_t)row * 64 + col) =
                            make_float2(v0, v1);
                    } else {
                        *(__half2*)(g_agh + (size_t)row * 64 + (col - 64)) =
                            __floats2half2_rn(v0, v1);
                    }
                }
            }
        }
    }
}

// ---------------------------------------------------------------------------
// Launch — prep forked onto a second stream, overlapped with the CSR build.
// ---------------------------------------------------------------------------
extern "C" void kernel_launch(void* const* d_in, const int* in_sizes, int n_in,
                              void* d_out, int out_size) {
    const float* x   = (const float*)d_in[0];
    const int*   ei  = (const int*)d_in[1];
    const float* Wl1 = (const float*)d_in[2];
    const float* Wr1 = (const float*)d_in[3];
    const float* b1  = (const float*)d_in[4];
    const float* Wl2 = (const float*)d_in[5];
    const float* Wr2 = (const float*)d_in[6];
    const float* b2  = (const float*)d_in[7];
    const float* Wl3 = (const float*)d_in[8];
    const float* Wr3 = (const float*)d_in[9];
    const float* b3  = (const float*)d_in[10];
    float* out = (float*)d_out;

    __half* w = nullptr;
    cudaGetSymbolAddress((void**)&w, g_w);

    const int ZB = 256;
    const int edge2Blocks = (NEDGES / 2 + ZB - 1) / ZB;     // 1563
    const int gathBlocks  = (NNODES * 32 + ZB - 1) / ZB;    // 6250
    const int gemmBlocks  = (NNODES + 127) / 128;           // 391
    const int SMEM0 = (2 * 128 * ROWA + 256 * ROWB) * 2;    // 106496
    const int SMEM1 = (2 * 128 * ROWA + 128 * ROWB) * 2;    //  71680

    cudaFuncSetAttribute(k_gemm_mma<0>,
                         cudaFuncAttributeMaxDynamicSharedMemorySize, SMEM0);
    cudaFuncSetAttribute(k_gemm_mma<1>,
                         cudaFuncAttributeMaxDynamicSharedMemorySize, SMEM1);

    cudaStream_t s2;
    cudaEvent_t eFork, eJoin;
    cudaStreamCreateWithFlags(&s2, cudaStreamNonBlocking);
    cudaEventCreateWithFlags(&eFork, cudaEventDisableTiming);
    cudaEventCreateWithFlags(&eJoin, cudaEventDisableTiming);

    // Main: zero, fork prep to s2, CSR chain here, join.
    k_zero<<<NBLK, ZB>>>();
    cudaEventRecord(eFork, 0);
    cudaStreamWaitEvent(s2, eFork, 0);
    k_prep<<<CONVBLK + WBLK, ZB, 0, s2>>>((const float4*)x,
                                          Wl1, Wr1, Wl2, Wr2, Wl3, Wr3);
    cudaEventRecord(eJoin, s2);

    k_count_deg2<<<edge2Blocks, ZB>>>(ei);
    k_scan_f<<<NBLK, ZB>>>();
    k_fill_csr2<<<edge2Blocks, ZB>>>(ei);

    cudaStreamWaitEvent(0, eJoin, 0);   // join before gather (needs g_xh)

    // ---- Layer 1 ----
    k_gather<<<gathBlocks, ZB>>>();
    k_gemm_mma<0><<<gemmBlocks, 256, SMEM0>>>(w + W_L1L, w + W_L1R, b1, nullptr);

    // ---- Layer 2 ----
    k_gather<<<gathBlocks, ZB>>>();
    k_gemm_mma<0><<<gemmBlocks, 256, SMEM0>>>(w + W_L2L, w + W_L2R, b2, nullptr);

    // ---- Layer 3: GEMM (partial out + y3), then 64-wide gather-add ----
    k_gemm_mma<1><<<gemmBlocks, 256, SMEM1>>>(w + W_L3L, nullptr, b3, out);
    k_gather64<<<gathBlocks, ZB>>>(out);
}